// round 3
// baseline (speedup 1.0000x reference)
#include <cuda_runtime.h>
#include <cuda_bf16.h>
#include <cstdint>

#define NC   4096
#define NS   16384
#define CCH  256
#define CS   128
#define DIN  384
#define HID  256

// Packed split-bf16 activation/weight buffers: row m = [hi(K) | lo(K)] bf16.
__device__ __align__(16) unsigned short g_ycat[(size_t)NS * (2 * DIN)];   // [16384][768]
__device__ __align__(16) unsigned short g_h[(size_t)NS * (2 * HID)];      // [16384][512]
__device__ __align__(16) unsigned short g_w1[(size_t)HID * (2 * DIN)];    // [256][768]  (W1^T split)
__device__ __align__(16) unsigned short g_w2[(size_t)HID * (2 * HID)];    // [256][512]  (W2^T split)

// ---------------------------------------------------------------------------
// helpers
// ---------------------------------------------------------------------------
__device__ __forceinline__ uint32_t smem_u32(const void* p) {
    uint32_t a;
    asm("{ .reg .u64 t; cvta.to.shared.u64 t, %1; cvt.u32.u64 %0, t; }" : "=r"(a) : "l"(p));
    return a;
}
__device__ __forceinline__ void cp16(uint32_t dst, const void* src) {
    asm volatile("cp.async.cg.shared.global [%0], [%1], 16;" :: "r"(dst), "l"(src));
}
__device__ __forceinline__ void cp_commit() { asm volatile("cp.async.commit_group;"); }
template<int N> __device__ __forceinline__ void cp_wait() {
    asm volatile("cp.async.wait_group %0;" :: "n"(N));
}
__device__ __forceinline__ void ldm4(uint32_t* r, uint32_t a) {
    asm volatile("ldmatrix.sync.aligned.m8n8.x4.shared.b16 {%0,%1,%2,%3}, [%4];"
                 : "=r"(r[0]), "=r"(r[1]), "=r"(r[2]), "=r"(r[3]) : "r"(a));
}
__device__ __forceinline__ void mma16816(float* c, const uint32_t* a, const uint32_t* b) {
    asm volatile("mma.sync.aligned.m16n8k16.row.col.f32.bf16.bf16.f32 "
                 "{%0,%1,%2,%3},{%4,%5,%6,%7},{%8,%9},{%0,%1,%2,%3};"
                 : "+f"(c[0]), "+f"(c[1]), "+f"(c[2]), "+f"(c[3])
                 : "r"(a[0]), "r"(a[1]), "r"(a[2]), "r"(a[3]), "r"(b[0]), "r"(b[1]));
}
__device__ __forceinline__ unsigned short f2bf(float v) {
    __nv_bfloat16 h = __float2bfloat16_rn(v);
    return __bfloat16_as_ushort(h);
}
__device__ __forceinline__ float bf2f(unsigned short u) {
    return __bfloat162float(__ushort_as_bfloat16(u));
}
// split float4 -> 4 hi bf16 (8B) + 4 lo bf16 (8B)
__device__ __forceinline__ void split_store4(unsigned short* hi, unsigned short* lo, float4 o) {
    unsigned short h0 = f2bf(o.x), h1 = f2bf(o.y), h2 = f2bf(o.z), h3 = f2bf(o.w);
    float l0 = o.x - bf2f(h0), l1 = o.y - bf2f(h1), l2 = o.z - bf2f(h2), l3 = o.w - bf2f(h3);
    uint2 hv, lv;
    hv.x = (uint32_t)h0 | ((uint32_t)h1 << 16);
    hv.y = (uint32_t)h2 | ((uint32_t)h3 << 16);
    lv.x = (uint32_t)f2bf(l0) | ((uint32_t)f2bf(l1) << 16);
    lv.y = (uint32_t)f2bf(l2) | ((uint32_t)f2bf(l3) << 16);
    *(uint2*)hi = hv;
    *(uint2*)lo = lv;
}

// ---------------------------------------------------------------------------
// Kernel 1: batch-segmented KNN (K=3) + interp + concat (packed bf16 hi/lo)
//           + fused weight transpose/split + fused tail outputs
// ---------------------------------------------------------------------------
__global__ __launch_bounds__(128)
void knn_interp_kernel(const float* __restrict__ x,
                       const float* __restrict__ pos,
                       const int*   __restrict__ batch,
                       const float* __restrict__ x_skip,
                       const float* __restrict__ pos_skip,
                       const int*   __restrict__ batch_skip,
                       const float* __restrict__ W1,
                       const float* __restrict__ W2,
                       float* __restrict__ out, int out_size)
{
    __shared__ int   sIdx[128][3];
    __shared__ float sW[128][3];

    const int tid = threadIdx.x;
    const int gi  = blockIdx.x * 128 + tid;

    // ---- fused weight prep: transpose + bf16 hi/lo split ----
    for (int i = gi; i < HID * DIN + HID * HID; i += NS) {
        if (i < HID * DIN) {
            int n = i / DIN, k = i % DIN;
            float v = W1[(size_t)k * HID + n];
            unsigned short h = f2bf(v);
            g_w1[(size_t)n * (2 * DIN) + k]       = h;
            g_w1[(size_t)n * (2 * DIN) + DIN + k] = f2bf(v - bf2f(h));
        } else {
            int j = i - HID * DIN;
            int n = j / HID, k = j % HID;
            float v = W2[(size_t)k * HID + n];
            unsigned short h = f2bf(v);
            g_w2[(size_t)n * (2 * HID) + k]       = h;
            g_w2[(size_t)n * (2 * HID) + HID + k] = f2bf(v - bf2f(h));
        }
    }

    // ---- phase 1: per-thread top-3 over own batch segment ----
    const float px = pos_skip[3 * gi + 0];
    const float py = pos_skip[3 * gi + 1];
    const float pz = pos_skip[3 * gi + 2];
    const int   mb = batch_skip[gi];

    int lo = 0, hi = NC;
    while (lo < hi) { int m = (lo + hi) >> 1; if (batch[m] < mb) lo = m + 1; else hi = m; }
    const int segs = lo;
    lo = segs; hi = NC;
    while (lo < hi) { int m = (lo + hi) >> 1; if (batch[m] <= mb) lo = m + 1; else hi = m; }
    const int sege = lo;

    float d0 = 3e38f, d1 = 3e38f, d2 = 3e38f;
    int   i0 = 0,     i1 = 0,     i2 = 0;

    for (int j = segs; j < sege; ++j) {
        float dx = pos[3 * j + 0] - px;
        float dy = pos[3 * j + 1] - py;
        float dz = pos[3 * j + 2] - pz;
        float d  = fmaf(dx, dx, fmaf(dy, dy, dz * dz));
        if (d < d2) {
            if (d < d1) {
                d2 = d1; i2 = i1;
                if (d < d0) { d1 = d0; i1 = i0; d0 = d; i0 = j; }
                else        { d1 = d;  i1 = j; }
            } else { d2 = d; i2 = j; }
        }
    }

    float w0 = 1.0f / fmaxf(d0, 1e-16f);
    float w1 = 1.0f / fmaxf(d1, 1e-16f);
    float w2 = 1.0f / fmaxf(d2, 1e-16f);
    float inv_sw = 1.0f / (w0 + w1 + w2);

    sIdx[tid][0] = i0; sIdx[tid][1] = i1; sIdx[tid][2] = i2;
    sW[tid][0] = w0 * inv_sw; sW[tid][1] = w1 * inv_sw; sW[tid][2] = w2 * inv_sw;

    // ---- fused tail outputs (pos_skip, batch_skip) ----
    if (out_size > NS * HID) {
        out[NS * HID + 3 * gi + 0] = px;
        out[NS * HID + 3 * gi + 1] = py;
        out[NS * HID + 3 * gi + 2] = pz;
        out[NS * HID + NS * 3 + gi] = (float)mb;
    }
    __syncthreads();

    // ---- phase 2: warp-cooperative gather + packed bf16 split store ----
    const int warp = tid >> 5;
    const int lane = tid & 31;

    for (int r = warp; r < 128; r += 4) {
        const int g  = blockIdx.x * 128 + r;
        const int j0 = sIdx[r][0], j1 = sIdx[r][1], j2 = sIdx[r][2];
        const float a = sW[r][0], b = sW[r][1], c = sW[r][2];

        const float4* X0 = (const float4*)(x + (size_t)j0 * CCH);
        const float4* X1 = (const float4*)(x + (size_t)j1 * CCH);
        const float4* X2 = (const float4*)(x + (size_t)j2 * CCH);
        unsigned short* Y = g_ycat + (size_t)g * (2 * DIN);

        #pragma unroll
        for (int v = lane; v < CCH / 4; v += 32) {
            float4 A = X0[v], B = X1[v], Cv = X2[v];
            float4 o;
            o.x = fmaf(a, A.x, fmaf(b, B.x, c * Cv.x));
            o.y = fmaf(a, A.y, fmaf(b, B.y, c * Cv.y));
            o.z = fmaf(a, A.z, fmaf(b, B.z, c * Cv.z));
            o.w = fmaf(a, A.w, fmaf(b, B.w, c * Cv.w));
            split_store4(Y + v * 4, Y + DIN + v * 4, o);
        }
        // skip features occupy cols 256..383
        float4 sv = ((const float4*)(x_skip + (size_t)g * CS))[lane];
        split_store4(Y + CCH + lane * 4, Y + DIN + CCH + lane * 4, sv);
    }
}

// ---------------------------------------------------------------------------
// bf16x3 mma.sync GEMM: C[M,256] = relu(A @ B^T + bias)
//   A packed [M][hi K | lo K] bf16, B packed [256][hi K | lo K] bf16 (W^T).
//   Computes Ahi*Bhi + Ahi*Blo + Alo*Bhi in fp32 accumulators.
// CTA tile 128x128, BK=32, 256 threads (8 warps = 4m x 2n), 3-stage cp.async.
// smem/stage: A 16KB + B 16KB; rows are 128B = [hi 32k | lo 32k], XOR-swizzled.
// ---------------------------------------------------------------------------
#define GSTAGES 3
#define GEMM_SMEM (GSTAGES * 32768)

template<int K, bool PACK>
__global__ __launch_bounds__(256, 1)
void mma_gemm(const unsigned short* __restrict__ Apk,
              const unsigned short* __restrict__ Bpk,
              const float* __restrict__ bias,
              void* __restrict__ Cout)
{
    constexpr int NCHK = K / 32;
    extern __shared__ uint8_t smem[];
    const uint32_t sb = smem_u32(smem);

    const int tid   = threadIdx.x;
    const int lane  = tid & 31;
    const int wid   = tid >> 5;
    const int warpM = wid & 3;        // 0..3 -> 32-row slice
    const int warpN = wid >> 2;       // 0..1 -> 64-col slice
    const int m0    = blockIdx.x * 128;
    const int n0    = blockIdx.y * 128;

    const uint8_t* Abytes = (const uint8_t*)Apk + (size_t)m0 * (4 * K);
    const uint8_t* Bbytes = (const uint8_t*)Bpk + (size_t)n0 * (4 * K);

    auto issue = [&](int kc, int st) {
        uint32_t sA = sb + st * 32768, sB = sA + 16384;
        #pragma unroll
        for (int i = 0; i < 4; ++i) {
            int id  = tid + 256 * i;
            int row = id >> 3, g = id & 7;
            int off = row * (4 * K) + (g < 4 ? kc * 64 + g * 16
                                             : 2 * K + kc * 64 + (g - 4) * 16);
            uint32_t d = (uint32_t)(row * 128) + (uint32_t)((g ^ (row & 7)) << 4);
            cp16(sA + d, Abytes + off);
            cp16(sB + d, Bbytes + off);
        }
        cp_commit();
    };

    // prologue: fill GSTAGES-1 stages
    issue(0, 0);
    issue(1, 1);

    float acc[2][8][4] = {};

    for (int c = 0; c < NCHK; ++c) {
        if (c <= NCHK - 2) cp_wait<1>(); else cp_wait<0>();
        __syncthreads();

        const int st = c % GSTAGES;
        const uint32_t sA = sb + st * 32768, sB = sA + 16384;

        #pragma unroll
        for (int kk = 0; kk < 2; ++kk) {
            uint32_t ah[2][4], al[2][4];
            #pragma unroll
            for (int mf = 0; mf < 2; ++mf) {
                const int rm  = warpM * 32 + mf * 16 + (lane & 15);
                const int sub = lane >> 4;
                const uint32_t base = sA + rm * 128;
                ldm4(ah[mf], base + (((kk * 2 + sub) ^ (rm & 7)) << 4));
                ldm4(al[mf], base + (((4 + kk * 2 + sub) ^ (rm & 7)) << 4));
            }
            uint32_t bh[8][2], bl[8][2];
            #pragma unroll
            for (int nq = 0; nq < 4; ++nq) {
                const int rn  = warpN * 64 + nq * 16 + (lane & 7) + ((lane >> 4) << 3);
                const int sub = (lane >> 3) & 1;
                const uint32_t base = sB + rn * 128;
                uint32_t t[4];
                ldm4(t, base + (((kk * 2 + sub) ^ (rn & 7)) << 4));
                bh[2 * nq][0] = t[0]; bh[2 * nq][1] = t[1];
                bh[2 * nq + 1][0] = t[2]; bh[2 * nq + 1][1] = t[3];
                ldm4(t, base + (((4 + kk * 2 + sub) ^ (rn & 7)) << 4));
                bl[2 * nq][0] = t[0]; bl[2 * nq][1] = t[1];
                bl[2 * nq + 1][0] = t[2]; bl[2 * nq + 1][1] = t[3];
            }
            #pragma unroll
            for (int mf = 0; mf < 2; ++mf)
                #pragma unroll
                for (int nf = 0; nf < 8; ++nf) {
                    mma16816(acc[mf][nf], ah[mf], bh[nf]);
                    mma16816(acc[mf][nf], ah[mf], bl[nf]);
                    mma16816(acc[mf][nf], al[mf], bh[nf]);
                }
        }

        if (c + GSTAGES - 1 < NCHK) issue(c + GSTAGES - 1, (c + GSTAGES - 1) % GSTAGES);
    }

    // ---- epilogue: bias + relu + store ----
    #pragma unroll
    for (int mf = 0; mf < 2; ++mf) {
        const int mrow = m0 + warpM * 32 + mf * 16 + (lane >> 2);
        #pragma unroll
        for (int nf = 0; nf < 8; ++nf) {
            const int n = n0 + warpN * 64 + nf * 8 + 2 * (lane & 3);
            const float b0v = __ldg(bias + n), b1v = __ldg(bias + n + 1);
            float v00 = fmaxf(acc[mf][nf][0] + b0v, 0.0f);
            float v01 = fmaxf(acc[mf][nf][1] + b1v, 0.0f);
            float v10 = fmaxf(acc[mf][nf][2] + b0v, 0.0f);
            float v11 = fmaxf(acc[mf][nf][3] + b1v, 0.0f);
            if (PACK) {
                // write h packed bf16 hi/lo for GEMM2: row stride 2*HID
                unsigned short* H = (unsigned short*)Cout;
                unsigned short h00 = f2bf(v00), h01 = f2bf(v01);
                unsigned short h10 = f2bf(v10), h11 = f2bf(v11);
                uint32_t hi0 = (uint32_t)h00 | ((uint32_t)h01 << 16);
                uint32_t lo0 = (uint32_t)f2bf(v00 - bf2f(h00)) | ((uint32_t)f2bf(v01 - bf2f(h01)) << 16);
                uint32_t hi1 = (uint32_t)h10 | ((uint32_t)h11 << 16);
                uint32_t lo1 = (uint32_t)f2bf(v10 - bf2f(h10)) | ((uint32_t)f2bf(v11 - bf2f(h11)) << 16);
                *(uint32_t*)(H + (size_t)mrow * (2 * HID) + n)             = hi0;
                *(uint32_t*)(H + (size_t)mrow * (2 * HID) + HID + n)       = lo0;
                *(uint32_t*)(H + (size_t)(mrow + 8) * (2 * HID) + n)       = hi1;
                *(uint32_t*)(H + (size_t)(mrow + 8) * (2 * HID) + HID + n) = lo1;
            } else {
                float* O = (float*)Cout;
                float2 p0 = {v00, v01}, p1 = {v10, v11};
                *(float2*)(O + (size_t)mrow * 256 + n)       = p0;
                *(float2*)(O + (size_t)(mrow + 8) * 256 + n) = p1;
            }
        }
    }
}

// ---------------------------------------------------------------------------
extern "C" void kernel_launch(void* const* d_in, const int* in_sizes, int n_in,
                              void* d_out, int out_size)
{
    const float* x          = (const float*)d_in[0];
    const float* pos        = (const float*)d_in[1];
    const int*   batch      = (const int*)  d_in[2];
    const float* x_skip     = (const float*)d_in[3];
    const float* pos_skip   = (const float*)d_in[4];
    const int*   batch_skip = (const int*)  d_in[5];
    const float* W1         = (const float*)d_in[6];
    const float* b1         = (const float*)d_in[7];
    const float* W2         = (const float*)d_in[8];
    const float* b2         = (const float*)d_in[9];
    float* out = (float*)d_out;

    unsigned short *ycat, *h, *w1, *w2;
    cudaGetSymbolAddress((void**)&ycat, g_ycat);
    cudaGetSymbolAddress((void**)&h,    g_h);
    cudaGetSymbolAddress((void**)&w1,   g_w1);
    cudaGetSymbolAddress((void**)&w2,   g_w2);

    cudaFuncSetAttribute(mma_gemm<DIN, true>,  cudaFuncAttributeMaxDynamicSharedMemorySize, GEMM_SMEM);
    cudaFuncSetAttribute(mma_gemm<HID, false>, cudaFuncAttributeMaxDynamicSharedMemorySize, GEMM_SMEM);

    // 1) KNN + interpolate + concat (+ weight prep + tail outputs)
    knn_interp_kernel<<<NS / 128, 128>>>(x, pos, batch, x_skip, pos_skip, batch_skip,
                                         W1, W2, out, out_size);

    // 2) h = relu(ycat @ W1 + b1)  — packed bf16 output
    {
        dim3 grid(NS / 128, 2);
        mma_gemm<DIN, true><<<grid, 256, GEMM_SMEM>>>(ycat, w1, b1, h);
    }
    // 3) out = relu(h @ W2 + b2)   — fp32 output
    {
        dim3 grid(NS / 128, 2);
        mma_gemm<HID, false><<<grid, 256, GEMM_SMEM>>>(h, w2, b2, out);
    }
}

// round 4
// speedup vs baseline: 2.3644x; 2.3644x over previous
#include <cuda_runtime.h>
#include <cuda_bf16.h>
#include <cstdint>

#define NC   4096
#define NS   16384
#define CCH  256
#define CS   128
#define DIN  384
#define HID  256

// Packed split-bf16 activation/weight buffers: row m = [hi(K) | lo(K)] bf16.
__device__ __align__(16) unsigned short g_ycat[(size_t)NS * (2 * DIN)];   // [16384][768]
__device__ __align__(16) unsigned short g_h[(size_t)NS * (2 * HID)];      // [16384][512]
__device__ __align__(16) unsigned short g_w1[(size_t)HID * (2 * DIN)];    // [256][768]  (W1^T split)
__device__ __align__(16) unsigned short g_w2[(size_t)HID * (2 * HID)];    // [256][512]  (W2^T split)

// ---------------------------------------------------------------------------
// helpers
// ---------------------------------------------------------------------------
__device__ __forceinline__ uint32_t smem_u32(const void* p) {
    uint32_t a;
    asm("{ .reg .u64 t; cvta.to.shared.u64 t, %1; cvt.u32.u64 %0, t; }" : "=r"(a) : "l"(p));
    return a;
}
__device__ __forceinline__ void cp16(uint32_t dst, const void* src) {
    asm volatile("cp.async.cg.shared.global [%0], [%1], 16;" :: "r"(dst), "l"(src));
}
__device__ __forceinline__ void cp_commit() { asm volatile("cp.async.commit_group;"); }
template<int N> __device__ __forceinline__ void cp_wait() {
    asm volatile("cp.async.wait_group %0;" :: "n"(N));
}
__device__ __forceinline__ void ldm4(uint32_t* r, uint32_t a) {
    asm volatile("ldmatrix.sync.aligned.m8n8.x4.shared.b16 {%0,%1,%2,%3}, [%4];"
                 : "=r"(r[0]), "=r"(r[1]), "=r"(r[2]), "=r"(r[3]) : "r"(a));
}
__device__ __forceinline__ void mma16816(float* c, const uint32_t* a, const uint32_t* b) {
    asm volatile("mma.sync.aligned.m16n8k16.row.col.f32.bf16.bf16.f32 "
                 "{%0,%1,%2,%3},{%4,%5,%6,%7},{%8,%9},{%0,%1,%2,%3};"
                 : "+f"(c[0]), "+f"(c[1]), "+f"(c[2]), "+f"(c[3])
                 : "r"(a[0]), "r"(a[1]), "r"(a[2]), "r"(a[3]), "r"(b[0]), "r"(b[1]));
}
__device__ __forceinline__ unsigned short f2bf(float v) {
    __nv_bfloat16 h = __float2bfloat16_rn(v);
    return __bfloat16_as_ushort(h);
}
__device__ __forceinline__ float bf2f(unsigned short u) {
    return __bfloat162float(__ushort_as_bfloat16(u));
}
__device__ __forceinline__ void split_store4(unsigned short* hi, unsigned short* lo, float4 o) {
    unsigned short h0 = f2bf(o.x), h1 = f2bf(o.y), h2 = f2bf(o.z), h3 = f2bf(o.w);
    float l0 = o.x - bf2f(h0), l1 = o.y - bf2f(h1), l2 = o.z - bf2f(h2), l3 = o.w - bf2f(h3);
    uint2 hv, lv;
    hv.x = (uint32_t)h0 | ((uint32_t)h1 << 16);
    hv.y = (uint32_t)h2 | ((uint32_t)h3 << 16);
    lv.x = (uint32_t)f2bf(l0) | ((uint32_t)f2bf(l1) << 16);
    lv.y = (uint32_t)f2bf(l2) | ((uint32_t)f2bf(l3) << 16);
    *(uint2*)hi = hv;
    *(uint2*)lo = lv;
}

// ---------------------------------------------------------------------------
// Kernel 1: KNN — 4 threads per fine point, branch-free top-3, shfl merge.
// 256 blocks x 256 threads; block handles 64 fine points.
// Also: coalesced-read weight transpose/split prep + tail outputs.
// ---------------------------------------------------------------------------
__global__ __launch_bounds__(256)
void knn_interp_kernel(const float* __restrict__ x,
                       const float* __restrict__ pos,
                       const int*   __restrict__ batch,
                       const float* __restrict__ x_skip,
                       const float* __restrict__ pos_skip,
                       const int*   __restrict__ batch_skip,
                       const float* __restrict__ W1,
                       const float* __restrict__ W2,
                       float* __restrict__ out, int out_size)
{
    __shared__ int   sIdx[64][3];
    __shared__ float sW[64][3];

    const int tid = threadIdx.x;
    const int p_local = tid >> 2;              // 0..63
    const int q       = tid & 3;               // scan part
    const int gp      = blockIdx.x * 64 + p_local;   // fine point id
    const int gid     = blockIdx.x * 256 + tid;      // global thread id

    // ---- weight prep: coalesced reads, scattered transposed writes ----
    for (int i = gid; i < DIN * HID; i += 256 * 256) {
        int k = i >> 8, n = i & 255;           // W1 is [DIN][HID] row-major
        float v = W1[i];
        unsigned short hh = f2bf(v);
        g_w1[(size_t)n * (2 * DIN) + k]       = hh;
        g_w1[(size_t)n * (2 * DIN) + DIN + k] = f2bf(v - bf2f(hh));
    }
    for (int i = gid; i < HID * HID; i += 256 * 256) {
        int k = i >> 8, n = i & 255;           // W2 is [HID][HID]
        float v = W2[i];
        unsigned short hh = f2bf(v);
        g_w2[(size_t)n * (2 * HID) + k]       = hh;
        g_w2[(size_t)n * (2 * HID) + HID + k] = f2bf(v - bf2f(hh));
    }

    // ---- phase 1: quarter-segment scan, branch-free top-3 ----
    const float px = pos_skip[3 * gp + 0];
    const float py = pos_skip[3 * gp + 1];
    const float pz = pos_skip[3 * gp + 2];
    const int   mb = batch_skip[gp];

    int lo = 0, hi = NC;
    while (lo < hi) { int m = (lo + hi) >> 1; if (batch[m] < mb) lo = m + 1; else hi = m; }
    const int segs = lo;
    lo = segs; hi = NC;
    while (lo < hi) { int m = (lo + hi) >> 1; if (batch[m] <= mb) lo = m + 1; else hi = m; }
    const int sege = lo;

    float d0 = 3e38f, d1 = 3e38f, d2 = 3e38f;
    int   i0 = segs,  i1 = segs,  i2 = segs;

    auto ins = [&](float dn, int jn) {
        bool b2 = dn < d2;
        float td = b2 ? dn : d2; int ti = b2 ? jn : i2;
        bool b1 = td < d1;
        d2 = b1 ? d1 : td; i2 = b1 ? i1 : ti;
        float ud = b1 ? td : d1; int ui = b1 ? ti : i1;
        bool b0 = ud < d0;
        d1 = b0 ? d0 : ud; i1 = b0 ? i0 : ui;
        d0 = b0 ? ud : d0; i0 = b0 ? ui : i0;
    };

    #pragma unroll 4
    for (int j = segs + q; j < sege; j += 4) {
        float dx = pos[3 * j + 0] - px;
        float dy = pos[3 * j + 1] - py;
        float dz = pos[3 * j + 2] - pz;
        float d  = fmaf(dx, dx, fmaf(dy, dy, dz * dz));
        ins(d, j);
    }

    // ---- merge across the 4 lanes of this point (xor 1, xor 2) ----
    #pragma unroll
    for (int m = 1; m <= 2; m <<= 1) {
        float e0 = __shfl_xor_sync(0xFFFFFFFFu, d0, m);
        float e1 = __shfl_xor_sync(0xFFFFFFFFu, d1, m);
        float e2 = __shfl_xor_sync(0xFFFFFFFFu, d2, m);
        int   f0 = __shfl_xor_sync(0xFFFFFFFFu, i0, m);
        int   f1 = __shfl_xor_sync(0xFFFFFFFFu, i1, m);
        int   f2 = __shfl_xor_sync(0xFFFFFFFFu, i2, m);
        ins(e0, f0); ins(e1, f1); ins(e2, f2);
    }

    if (q == 0) {
        float w0 = 1.0f / fmaxf(d0, 1e-16f);
        float w1v = 1.0f / fmaxf(d1, 1e-16f);
        float w2v = 1.0f / fmaxf(d2, 1e-16f);
        float inv_sw = 1.0f / (w0 + w1v + w2v);
        sIdx[p_local][0] = i0; sIdx[p_local][1] = i1; sIdx[p_local][2] = i2;
        sW[p_local][0] = w0 * inv_sw; sW[p_local][1] = w1v * inv_sw; sW[p_local][2] = w2v * inv_sw;

        // tail outputs (pos_skip, batch_skip) if flattened tuple expected
        if (out_size > NS * HID) {
            out[NS * HID + 3 * gp + 0] = px;
            out[NS * HID + 3 * gp + 1] = py;
            out[NS * HID + 3 * gp + 2] = pz;
            out[NS * HID + NS * 3 + gp] = (float)mb;
        }
    }
    __syncthreads();

    // ---- phase 2: warp-cooperative gather + packed bf16 split store ----
    const int warp = tid >> 5;
    const int lane = tid & 31;

    for (int r = warp; r < 64; r += 8) {
        const int g  = blockIdx.x * 64 + r;
        const int j0 = sIdx[r][0], j1 = sIdx[r][1], j2 = sIdx[r][2];
        const float a = sW[r][0], b = sW[r][1], c = sW[r][2];

        const float4* X0 = (const float4*)(x + (size_t)j0 * CCH);
        const float4* X1 = (const float4*)(x + (size_t)j1 * CCH);
        const float4* X2 = (const float4*)(x + (size_t)j2 * CCH);
        unsigned short* Y = g_ycat + (size_t)g * (2 * DIN);

        #pragma unroll
        for (int v = lane; v < CCH / 4; v += 32) {
            float4 A = X0[v], B = X1[v], Cv = X2[v];
            float4 o;
            o.x = fmaf(a, A.x, fmaf(b, B.x, c * Cv.x));
            o.y = fmaf(a, A.y, fmaf(b, B.y, c * Cv.y));
            o.z = fmaf(a, A.z, fmaf(b, B.z, c * Cv.z));
            o.w = fmaf(a, A.w, fmaf(b, B.w, c * Cv.w));
            split_store4(Y + v * 4, Y + DIN + v * 4, o);
        }
        float4 sv = ((const float4*)(x_skip + (size_t)g * CS))[lane];
        split_store4(Y + CCH + lane * 4, Y + DIN + CCH + lane * 4, sv);
    }
}

// ---------------------------------------------------------------------------
// bf16x3 mma.sync GEMM: C[M,256] = relu(A @ B^T + bias)
// CTA tile 128x128, BK=32, 256 threads (8 warps = 4m x 2n), 3-stage cp.async.
// ---------------------------------------------------------------------------
#define GSTAGES 3
#define GEMM_SMEM (GSTAGES * 32768)

template<int K, bool PACK>
__global__ __launch_bounds__(256, 1)
void mma_gemm(const unsigned short* __restrict__ Apk,
              const unsigned short* __restrict__ Bpk,
              const float* __restrict__ bias,
              void* __restrict__ Cout)
{
    constexpr int NCHK = K / 32;
    extern __shared__ uint8_t smem[];
    const uint32_t sb = smem_u32(smem);

    const int tid   = threadIdx.x;
    const int lane  = tid & 31;
    const int wid   = tid >> 5;
    const int warpM = wid & 3;
    const int warpN = wid >> 2;
    const int m0    = blockIdx.x * 128;
    const int n0    = blockIdx.y * 128;

    const uint8_t* Abytes = (const uint8_t*)Apk + (size_t)m0 * (4 * K);
    const uint8_t* Bbytes = (const uint8_t*)Bpk + (size_t)n0 * (4 * K);

    auto issue = [&](int kc, int st) {
        uint32_t sA = sb + st * 32768, sB = sA + 16384;
        #pragma unroll
        for (int i = 0; i < 4; ++i) {
            int id  = tid + 256 * i;
            int row = id >> 3, g = id & 7;
            int off = row * (4 * K) + (g < 4 ? kc * 64 + g * 16
                                             : 2 * K + kc * 64 + (g - 4) * 16);
            uint32_t d = (uint32_t)(row * 128) + (uint32_t)((g ^ (row & 7)) << 4);
            cp16(sA + d, Abytes + off);
            cp16(sB + d, Bbytes + off);
        }
        cp_commit();
    };

    issue(0, 0);
    issue(1, 1);

    float acc[2][8][4] = {};

    for (int c = 0; c < NCHK; ++c) {
        if (c <= NCHK - 2) cp_wait<1>(); else cp_wait<0>();
        __syncthreads();

        const int st = c % GSTAGES;
        const uint32_t sA = sb + st * 32768, sB = sA + 16384;

        #pragma unroll
        for (int kk = 0; kk < 2; ++kk) {
            uint32_t ah[2][4], al[2][4];
            #pragma unroll
            for (int mf = 0; mf < 2; ++mf) {
                const int rm  = warpM * 32 + mf * 16 + (lane & 15);
                const int sub = lane >> 4;
                const uint32_t base = sA + rm * 128;
                ldm4(ah[mf], base + (((kk * 2 + sub) ^ (rm & 7)) << 4));
                ldm4(al[mf], base + (((4 + kk * 2 + sub) ^ (rm & 7)) << 4));
            }
            uint32_t bh[8][2], bl[8][2];
            #pragma unroll
            for (int nq = 0; nq < 4; ++nq) {
                const int rn  = warpN * 64 + nq * 16 + (lane & 7) + ((lane >> 4) << 3);
                const int sub = (lane >> 3) & 1;
                const uint32_t base = sB + rn * 128;
                uint32_t t[4];
                ldm4(t, base + (((kk * 2 + sub) ^ (rn & 7)) << 4));
                bh[2 * nq][0] = t[0]; bh[2 * nq][1] = t[1];
                bh[2 * nq + 1][0] = t[2]; bh[2 * nq + 1][1] = t[3];
                ldm4(t, base + (((4 + kk * 2 + sub) ^ (rn & 7)) << 4));
                bl[2 * nq][0] = t[0]; bl[2 * nq][1] = t[1];
                bl[2 * nq + 1][0] = t[2]; bl[2 * nq + 1][1] = t[3];
            }
            #pragma unroll
            for (int mf = 0; mf < 2; ++mf)
                #pragma unroll
                for (int nf = 0; nf < 8; ++nf) {
                    mma16816(acc[mf][nf], ah[mf], bh[nf]);
                    mma16816(acc[mf][nf], ah[mf], bl[nf]);
                    mma16816(acc[mf][nf], al[mf], bh[nf]);
                }
        }

        if (c + GSTAGES - 1 < NCHK) issue(c + GSTAGES - 1, (c + GSTAGES - 1) % GSTAGES);
    }

    #pragma unroll
    for (int mf = 0; mf < 2; ++mf) {
        const int mrow = m0 + warpM * 32 + mf * 16 + (lane >> 2);
        #pragma unroll
        for (int nf = 0; nf < 8; ++nf) {
            const int n = n0 + warpN * 64 + nf * 8 + 2 * (lane & 3);
            const float b0v = __ldg(bias + n), b1v = __ldg(bias + n + 1);
            float v00 = fmaxf(acc[mf][nf][0] + b0v, 0.0f);
            float v01 = fmaxf(acc[mf][nf][1] + b1v, 0.0f);
            float v10 = fmaxf(acc[mf][nf][2] + b0v, 0.0f);
            float v11 = fmaxf(acc[mf][nf][3] + b1v, 0.0f);
            if (PACK) {
                unsigned short* H = (unsigned short*)Cout;
                unsigned short h00 = f2bf(v00), h01 = f2bf(v01);
                unsigned short h10 = f2bf(v10), h11 = f2bf(v11);
                uint32_t hi0 = (uint32_t)h00 | ((uint32_t)h01 << 16);
                uint32_t lo0 = (uint32_t)f2bf(v00 - bf2f(h00)) | ((uint32_t)f2bf(v01 - bf2f(h01)) << 16);
                uint32_t hi1 = (uint32_t)h10 | ((uint32_t)h11 << 16);
                uint32_t lo1 = (uint32_t)f2bf(v10 - bf2f(h10)) | ((uint32_t)f2bf(v11 - bf2f(h11)) << 16);
                *(uint32_t*)(H + (size_t)mrow * (2 * HID) + n)             = hi0;
                *(uint32_t*)(H + (size_t)mrow * (2 * HID) + HID + n)       = lo0;
                *(uint32_t*)(H + (size_t)(mrow + 8) * (2 * HID) + n)       = hi1;
                *(uint32_t*)(H + (size_t)(mrow + 8) * (2 * HID) + HID + n) = lo1;
            } else {
                float* O = (float*)Cout;
                float2 p0 = {v00, v01}, p1 = {v10, v11};
                *(float2*)(O + (size_t)mrow * 256 + n)       = p0;
                *(float2*)(O + (size_t)(mrow + 8) * 256 + n) = p1;
            }
        }
    }
}

// ---------------------------------------------------------------------------
extern "C" void kernel_launch(void* const* d_in, const int* in_sizes, int n_in,
                              void* d_out, int out_size)
{
    const float* x          = (const float*)d_in[0];
    const float* pos        = (const float*)d_in[1];
    const int*   batch      = (const int*)  d_in[2];
    const float* x_skip     = (const float*)d_in[3];
    const float* pos_skip   = (const float*)d_in[4];
    const int*   batch_skip = (const int*)  d_in[5];
    const float* W1         = (const float*)d_in[6];
    const float* b1         = (const float*)d_in[7];
    const float* W2         = (const float*)d_in[8];
    const float* b2         = (const float*)d_in[9];
    float* out = (float*)d_out;

    unsigned short *ycat, *h, *w1, *w2;
    cudaGetSymbolAddress((void**)&ycat, g_ycat);
    cudaGetSymbolAddress((void**)&h,    g_h);
    cudaGetSymbolAddress((void**)&w1,   g_w1);
    cudaGetSymbolAddress((void**)&w2,   g_w2);

    cudaFuncSetAttribute(mma_gemm<DIN, true>,  cudaFuncAttributeMaxDynamicSharedMemorySize, GEMM_SMEM);
    cudaFuncSetAttribute(mma_gemm<HID, false>, cudaFuncAttributeMaxDynamicSharedMemorySize, GEMM_SMEM);

    // 1) KNN + interpolate + concat (+ weight prep + tail outputs)
    knn_interp_kernel<<<NS / 64, 256>>>(x, pos, batch, x_skip, pos_skip, batch_skip,
                                        W1, W2, out, out_size);

    // 2) h = relu(ycat @ W1 + b1)  — packed bf16 output
    {
        dim3 grid(NS / 128, 2);
        mma_gemm<DIN, true><<<grid, 256, GEMM_SMEM>>>(ycat, w1, b1, h);
    }
    // 3) out = relu(h @ W2 + b2)   — fp32 output
    {
        dim3 grid(NS / 128, 2);
        mma_gemm<HID, false><<<grid, 256, GEMM_SMEM>>>(h, w2, b2, out);
    }
}

// round 5
// speedup vs baseline: 2.6880x; 1.1369x over previous
#include <cuda_runtime.h>
#include <cuda_bf16.h>
#include <cstdint>

#define NC   4096
#define NS   16384
#define CCH  256
#define CS   128
#define DIN  384
#define HID  256

// Packed split-bf16 activation/weight buffers: row m = [hi(K) | lo(K)] bf16.
__device__ __align__(16) unsigned short g_ycat[(size_t)NS * (2 * DIN)];
__device__ __align__(16) unsigned short g_h[(size_t)NS * (2 * HID)];
__device__ __align__(16) unsigned short g_w1[(size_t)HID * (2 * DIN)];
__device__ __align__(16) unsigned short g_w2[(size_t)HID * (2 * HID)];

// ---------------------------------------------------------------------------
// helpers
// ---------------------------------------------------------------------------
__device__ __forceinline__ uint32_t smem_u32(const void* p) {
    uint32_t a;
    asm("{ .reg .u64 t; cvta.to.shared.u64 t, %1; cvt.u32.u64 %0, t; }" : "=r"(a) : "l"(p));
    return a;
}
__device__ __forceinline__ void cp16(uint32_t dst, const void* src) {
    asm volatile("cp.async.cg.shared.global [%0], [%1], 16;" :: "r"(dst), "l"(src));
}
__device__ __forceinline__ void cp_commit() { asm volatile("cp.async.commit_group;"); }
template<int N> __device__ __forceinline__ void cp_wait() {
    asm volatile("cp.async.wait_group %0;" :: "n"(N));
}
__device__ __forceinline__ void ldm4(uint32_t* r, uint32_t a) {
    asm volatile("ldmatrix.sync.aligned.m8n8.x4.shared.b16 {%0,%1,%2,%3}, [%4];"
                 : "=r"(r[0]), "=r"(r[1]), "=r"(r[2]), "=r"(r[3]) : "r"(a));
}
__device__ __forceinline__ void mma16816(float* c, const uint32_t* a, const uint32_t* b) {
    asm volatile("mma.sync.aligned.m16n8k16.row.col.f32.bf16.bf16.f32 "
                 "{%0,%1,%2,%3},{%4,%5,%6,%7},{%8,%9},{%0,%1,%2,%3};"
                 : "+f"(c[0]), "+f"(c[1]), "+f"(c[2]), "+f"(c[3])
                 : "r"(a[0]), "r"(a[1]), "r"(a[2]), "r"(a[3]), "r"(b[0]), "r"(b[1]));
}
__device__ __forceinline__ unsigned short f2bf(float v) {
    __nv_bfloat16 h = __float2bfloat16_rn(v);
    return __bfloat16_as_ushort(h);
}
__device__ __forceinline__ float bf2f(unsigned short u) {
    return __bfloat162float(__ushort_as_bfloat16(u));
}
__device__ __forceinline__ void split_store4(unsigned short* hi, unsigned short* lo, float4 o) {
    unsigned short h0 = f2bf(o.x), h1 = f2bf(o.y), h2 = f2bf(o.z), h3 = f2bf(o.w);
    float l0 = o.x - bf2f(h0), l1 = o.y - bf2f(h1), l2 = o.z - bf2f(h2), l3 = o.w - bf2f(h3);
    uint2 hv, lv;
    hv.x = (uint32_t)h0 | ((uint32_t)h1 << 16);
    hv.y = (uint32_t)h2 | ((uint32_t)h3 << 16);
    lv.x = (uint32_t)f2bf(l0) | ((uint32_t)f2bf(l1) << 16);
    lv.y = (uint32_t)f2bf(l2) | ((uint32_t)f2bf(l3) << 16);
    *(uint2*)hi = hv;
    *(uint2*)lo = lv;
}

// ---------------------------------------------------------------------------
// Kernel 1: KNN — smem-resident coarse pos4, 8 threads/point, dot-form rank,
// rare-branch top-3 insertion, shfl merge. 512 blocks x 256 thr (32 pts/blk).
// ---------------------------------------------------------------------------
#define KNN_SMEM (NC * 16)   // 64KB: float4 (x,y,z,|c|^2) per coarse point

__global__ __launch_bounds__(256)
void knn_interp_kernel(const float* __restrict__ x,
                       const float* __restrict__ pos,
                       const int*   __restrict__ batch,
                       const float* __restrict__ x_skip,
                       const float* __restrict__ pos_skip,
                       const int*   __restrict__ batch_skip,
                       const float* __restrict__ W1,
                       const float* __restrict__ W2,
                       float* __restrict__ out, int out_size)
{
    extern __shared__ float4 pos4[];           // [NC]
    __shared__ int   sIdx[32][3];
    __shared__ float sW[32][3];

    const int tid = threadIdx.x;
    const int p_local = tid >> 3;              // 0..31
    const int q       = tid & 7;               // scan part 0..7
    const int gp      = blockIdx.x * 32 + p_local;
    const int gid     = blockIdx.x * 256 + tid;

    // ---- fill smem pos4 ----
    for (int j = tid; j < NC; j += 256) {
        float cx = pos[3 * j + 0], cy = pos[3 * j + 1], cz = pos[3 * j + 2];
        pos4[j] = make_float4(cx, cy, cz, fmaf(cx, cx, fmaf(cy, cy, cz * cz)));
    }

    // ---- weight prep: coalesced reads, scattered transposed writes ----
    for (int i = gid; i < DIN * HID; i += 512 * 256) {
        int k = i >> 8, n = i & 255;
        float v = W1[i];
        unsigned short hh = f2bf(v);
        g_w1[(size_t)n * (2 * DIN) + k]       = hh;
        g_w1[(size_t)n * (2 * DIN) + DIN + k] = f2bf(v - bf2f(hh));
    }
    for (int i = gid; i < HID * HID; i += 512 * 256) {
        int k = i >> 8, n = i & 255;
        float v = W2[i];
        unsigned short hh = f2bf(v);
        g_w2[(size_t)n * (2 * HID) + k]       = hh;
        g_w2[(size_t)n * (2 * HID) + HID + k] = f2bf(v - bf2f(hh));
    }

    const float px = pos_skip[3 * gp + 0];
    const float py = pos_skip[3 * gp + 1];
    const float pz = pos_skip[3 * gp + 2];
    const int   mb = batch_skip[gp];

    int lo = 0, hi = NC;
    while (lo < hi) { int m = (lo + hi) >> 1; if (batch[m] < mb) lo = m + 1; else hi = m; }
    const int segs = lo;
    lo = segs; hi = NC;
    while (lo < hi) { int m = (lo + hi) >> 1; if (batch[m] <= mb) lo = m + 1; else hi = m; }
    const int sege = lo;

    __syncthreads();

    // ---- phase 1: eighth-segment scan on d' = |c|^2 - 2 p.c ----
    const float nx = -2.0f * px, ny = -2.0f * py, nz = -2.0f * pz;
    float d0 = 3e38f, d1 = 3e38f, d2 = 3e38f;
    int   i0 = segs,  i1 = segs,  i2 = segs;

    auto ins = [&](float dn, int jn) {
        bool b2 = dn < d2;
        float td = b2 ? dn : d2; int ti = b2 ? jn : i2;
        bool b1 = td < d1;
        d2 = b1 ? d1 : td; i2 = b1 ? i1 : ti;
        float ud = b1 ? td : d1; int ui = b1 ? ti : i1;
        bool b0 = ud < d0;
        d1 = b0 ? d0 : ud; i1 = b0 ? i0 : ui;
        d0 = b0 ? ud : d0; i0 = b0 ? ui : i0;
    };

    #pragma unroll 4
    for (int j = segs + q; j < sege; j += 8) {
        float4 c = pos4[j];
        float s = fmaf(nx, c.x, fmaf(ny, c.y, fmaf(nz, c.z, c.w)));
        if (s < d2) ins(s, j);      // rare
    }

    // ---- merge across the 8 lanes of this point ----
    #pragma unroll
    for (int m = 1; m <= 4; m <<= 1) {
        float e0 = __shfl_xor_sync(0xFFFFFFFFu, d0, m);
        float e1 = __shfl_xor_sync(0xFFFFFFFFu, d1, m);
        float e2 = __shfl_xor_sync(0xFFFFFFFFu, d2, m);
        int   f0 = __shfl_xor_sync(0xFFFFFFFFu, i0, m);
        int   f1 = __shfl_xor_sync(0xFFFFFFFFu, i1, m);
        int   f2 = __shfl_xor_sync(0xFFFFFFFFu, i2, m);
        ins(e0, f0); ins(e1, f1); ins(e2, f2);
    }

    if (q == 0) {
        // exact squared distances for the 3 winners (match reference weights)
        float4 c0 = pos4[i0], c1 = pos4[i1], c2 = pos4[i2];
        float ax = c0.x - px, ay = c0.y - py, az = c0.z - pz;
        float bx = c1.x - px, by = c1.y - py, bz = c1.z - pz;
        float cx = c2.x - px, cy = c2.y - py, cz = c2.z - pz;
        float e0 = fmaf(ax, ax, fmaf(ay, ay, az * az));
        float e1 = fmaf(bx, bx, fmaf(by, by, bz * bz));
        float e2 = fmaf(cx, cx, fmaf(cy, cy, cz * cz));
        float w0 = 1.0f / fmaxf(e0, 1e-16f);
        float w1v = 1.0f / fmaxf(e1, 1e-16f);
        float w2v = 1.0f / fmaxf(e2, 1e-16f);
        float inv_sw = 1.0f / (w0 + w1v + w2v);
        sIdx[p_local][0] = i0; sIdx[p_local][1] = i1; sIdx[p_local][2] = i2;
        sW[p_local][0] = w0 * inv_sw; sW[p_local][1] = w1v * inv_sw; sW[p_local][2] = w2v * inv_sw;

        if (out_size > NS * HID) {
            out[NS * HID + 3 * gp + 0] = px;
            out[NS * HID + 3 * gp + 1] = py;
            out[NS * HID + 3 * gp + 2] = pz;
            out[NS * HID + NS * 3 + gp] = (float)mb;
        }
    }
    __syncthreads();

    // ---- phase 2: warp-cooperative gather + packed bf16 split store ----
    const int warp = tid >> 5;
    const int lane = tid & 31;

    for (int r = warp; r < 32; r += 8) {
        const int g  = blockIdx.x * 32 + r;
        const int j0 = sIdx[r][0], j1 = sIdx[r][1], j2 = sIdx[r][2];
        const float a = sW[r][0], b = sW[r][1], c = sW[r][2];

        const float4* X0 = (const float4*)(x + (size_t)j0 * CCH);
        const float4* X1 = (const float4*)(x + (size_t)j1 * CCH);
        const float4* X2 = (const float4*)(x + (size_t)j2 * CCH);
        unsigned short* Y = g_ycat + (size_t)g * (2 * DIN);

        #pragma unroll
        for (int v = lane; v < CCH / 4; v += 32) {
            float4 A = X0[v], B = X1[v], Cv = X2[v];
            float4 o;
            o.x = fmaf(a, A.x, fmaf(b, B.x, c * Cv.x));
            o.y = fmaf(a, A.y, fmaf(b, B.y, c * Cv.y));
            o.z = fmaf(a, A.z, fmaf(b, B.z, c * Cv.z));
            o.w = fmaf(a, A.w, fmaf(b, B.w, c * Cv.w));
            split_store4(Y + v * 4, Y + DIN + v * 4, o);
        }
        float4 sv = ((const float4*)(x_skip + (size_t)g * CS))[lane];
        split_store4(Y + CCH + lane * 4, Y + DIN + CCH + lane * 4, sv);
    }
}

// ---------------------------------------------------------------------------
// bf16x3 mma.sync GEMM: C[M,256] = relu(A @ B^T + bias)
// CTA tile 128x128, BK=32, 256 threads (8 warps = 4m x 2n), 3-stage cp.async.
// ---------------------------------------------------------------------------
#define GSTAGES 3
#define GEMM_SMEM (GSTAGES * 32768)

template<int K, bool PACK>
__global__ __launch_bounds__(256, 1)
void mma_gemm(const unsigned short* __restrict__ Apk,
              const unsigned short* __restrict__ Bpk,
              const float* __restrict__ bias,
              void* __restrict__ Cout)
{
    constexpr int NCHK = K / 32;
    extern __shared__ uint8_t smem[];
    const uint32_t sb = smem_u32(smem);

    const int tid   = threadIdx.x;
    const int lane  = tid & 31;
    const int wid   = tid >> 5;
    const int warpM = wid & 3;
    const int warpN = wid >> 2;
    const int m0    = blockIdx.x * 128;
    const int n0    = blockIdx.y * 128;

    const uint8_t* Abytes = (const uint8_t*)Apk + (size_t)m0 * (4 * K);
    const uint8_t* Bbytes = (const uint8_t*)Bpk + (size_t)n0 * (4 * K);

    auto issue = [&](int kc, int st) {
        uint32_t sA = sb + st * 32768, sB = sA + 16384;
        #pragma unroll
        for (int i = 0; i < 4; ++i) {
            int id  = tid + 256 * i;
            int row = id >> 3, g = id & 7;
            int off = row * (4 * K) + (g < 4 ? kc * 64 + g * 16
                                             : 2 * K + kc * 64 + (g - 4) * 16);
            uint32_t d = (uint32_t)(row * 128) + (uint32_t)((g ^ (row & 7)) << 4);
            cp16(sA + d, Abytes + off);
            cp16(sB + d, Bbytes + off);
        }
        cp_commit();
    };

    issue(0, 0);
    issue(1, 1);

    float acc[2][8][4] = {};

    for (int c = 0; c < NCHK; ++c) {
        if (c <= NCHK - 2) cp_wait<1>(); else cp_wait<0>();
        __syncthreads();

        const int st = c % GSTAGES;
        const uint32_t sA = sb + st * 32768, sB = sA + 16384;

        #pragma unroll
        for (int kk = 0; kk < 2; ++kk) {
            uint32_t ah[2][4], al[2][4];
            #pragma unroll
            for (int mf = 0; mf < 2; ++mf) {
                const int rm  = warpM * 32 + mf * 16 + (lane & 15);
                const int sub = lane >> 4;
                const uint32_t base = sA + rm * 128;
                ldm4(ah[mf], base + (((kk * 2 + sub) ^ (rm & 7)) << 4));
                ldm4(al[mf], base + (((4 + kk * 2 + sub) ^ (rm & 7)) << 4));
            }
            uint32_t bh[8][2], bl[8][2];
            #pragma unroll
            for (int nq = 0; nq < 4; ++nq) {
                const int rn  = warpN * 64 + nq * 16 + (lane & 7) + ((lane >> 4) << 3);
                const int sub = (lane >> 3) & 1;
                const uint32_t base = sB + rn * 128;
                uint32_t t[4];
                ldm4(t, base + (((kk * 2 + sub) ^ (rn & 7)) << 4));
                bh[2 * nq][0] = t[0]; bh[2 * nq][1] = t[1];
                bh[2 * nq + 1][0] = t[2]; bh[2 * nq + 1][1] = t[3];
                ldm4(t, base + (((4 + kk * 2 + sub) ^ (rn & 7)) << 4));
                bl[2 * nq][0] = t[0]; bl[2 * nq][1] = t[1];
                bl[2 * nq + 1][0] = t[2]; bl[2 * nq + 1][1] = t[3];
            }
            #pragma unroll
            for (int mf = 0; mf < 2; ++mf)
                #pragma unroll
                for (int nf = 0; nf < 8; ++nf) {
                    mma16816(acc[mf][nf], ah[mf], bh[nf]);
                    mma16816(acc[mf][nf], ah[mf], bl[nf]);
                    mma16816(acc[mf][nf], al[mf], bh[nf]);
                }
        }

        if (c + GSTAGES - 1 < NCHK) issue(c + GSTAGES - 1, (c + GSTAGES - 1) % GSTAGES);
    }

    #pragma unroll
    for (int mf = 0; mf < 2; ++mf) {
        const int mrow = m0 + warpM * 32 + mf * 16 + (lane >> 2);
        #pragma unroll
        for (int nf = 0; nf < 8; ++nf) {
            const int n = n0 + warpN * 64 + nf * 8 + 2 * (lane & 3);
            const float b0v = __ldg(bias + n), b1v = __ldg(bias + n + 1);
            float v00 = fmaxf(acc[mf][nf][0] + b0v, 0.0f);
            float v01 = fmaxf(acc[mf][nf][1] + b1v, 0.0f);
            float v10 = fmaxf(acc[mf][nf][2] + b0v, 0.0f);
            float v11 = fmaxf(acc[mf][nf][3] + b1v, 0.0f);
            if (PACK) {
                unsigned short* H = (unsigned short*)Cout;
                unsigned short h00 = f2bf(v00), h01 = f2bf(v01);
                unsigned short h10 = f2bf(v10), h11 = f2bf(v11);
                uint32_t hi0 = (uint32_t)h00 | ((uint32_t)h01 << 16);
                uint32_t lo0 = (uint32_t)f2bf(v00 - bf2f(h00)) | ((uint32_t)f2bf(v01 - bf2f(h01)) << 16);
                uint32_t hi1 = (uint32_t)h10 | ((uint32_t)h11 << 16);
                uint32_t lo1 = (uint32_t)f2bf(v10 - bf2f(h10)) | ((uint32_t)f2bf(v11 - bf2f(h11)) << 16);
                *(uint32_t*)(H + (size_t)mrow * (2 * HID) + n)             = hi0;
                *(uint32_t*)(H + (size_t)mrow * (2 * HID) + HID + n)       = lo0;
                *(uint32_t*)(H + (size_t)(mrow + 8) * (2 * HID) + n)       = hi1;
                *(uint32_t*)(H + (size_t)(mrow + 8) * (2 * HID) + HID + n) = lo1;
            } else {
                float* O = (float*)Cout;
                float2 p0 = {v00, v01}, p1 = {v10, v11};
                *(float2*)(O + (size_t)mrow * 256 + n)       = p0;
                *(float2*)(O + (size_t)(mrow + 8) * 256 + n) = p1;
            }
        }
    }
}

// ---------------------------------------------------------------------------
extern "C" void kernel_launch(void* const* d_in, const int* in_sizes, int n_in,
                              void* d_out, int out_size)
{
    const float* x          = (const float*)d_in[0];
    const float* pos        = (const float*)d_in[1];
    const int*   batch      = (const int*)  d_in[2];
    const float* x_skip     = (const float*)d_in[3];
    const float* pos_skip   = (const float*)d_in[4];
    const int*   batch_skip = (const int*)  d_in[5];
    const float* W1         = (const float*)d_in[6];
    const float* b1         = (const float*)d_in[7];
    const float* W2         = (const float*)d_in[8];
    const float* b2         = (const float*)d_in[9];
    float* out = (float*)d_out;

    unsigned short *ycat, *h, *w1, *w2;
    cudaGetSymbolAddress((void**)&ycat, g_ycat);
    cudaGetSymbolAddress((void**)&h,    g_h);
    cudaGetSymbolAddress((void**)&w1,   g_w1);
    cudaGetSymbolAddress((void**)&w2,   g_w2);

    cudaFuncSetAttribute(knn_interp_kernel,   cudaFuncAttributeMaxDynamicSharedMemorySize, KNN_SMEM);
    cudaFuncSetAttribute(mma_gemm<DIN, true>,  cudaFuncAttributeMaxDynamicSharedMemorySize, GEMM_SMEM);
    cudaFuncSetAttribute(mma_gemm<HID, false>, cudaFuncAttributeMaxDynamicSharedMemorySize, GEMM_SMEM);

    // 1) KNN + interpolate + concat (+ weight prep + tail outputs)
    knn_interp_kernel<<<NS / 32, 256, KNN_SMEM>>>(x, pos, batch, x_skip, pos_skip, batch_skip,
                                                  W1, W2, out, out_size);

    // 2) h = relu(ycat @ W1 + b1)  — packed bf16 output
    {
        dim3 grid(NS / 128, 2);
        mma_gemm<DIN, true><<<grid, 256, GEMM_SMEM>>>(ycat, w1, b1, h);
    }
    // 3) out = relu(h @ W2 + b2)   — fp32 output
    {
        dim3 grid(NS / 128, 2);
        mma_gemm<HID, false><<<grid, 256, GEMM_SMEM>>>(h, w2, b2, out);
    }
}

// round 6
// speedup vs baseline: 3.0227x; 1.1245x over previous
#include <cuda_runtime.h>
#include <cuda_bf16.h>
#include <cstdint>

#define NC   4096
#define NS   16384
#define CCH  256
#define CS   128
#define DIN  384
#define HID  256

// Packed split-bf16 activation/weight buffers: row m = [hi(K) | lo(K)] bf16.
__device__ __align__(16) unsigned short g_ycat[(size_t)NS * (2 * DIN)];
__device__ __align__(16) unsigned short g_h[(size_t)NS * (2 * HID)];
__device__ __align__(16) unsigned short g_w1[(size_t)HID * (2 * DIN)];
__device__ __align__(16) unsigned short g_w2[(size_t)HID * (2 * HID)];

// ---------------------------------------------------------------------------
// helpers
// ---------------------------------------------------------------------------
__device__ __forceinline__ uint32_t smem_u32(const void* p) {
    uint32_t a;
    asm("{ .reg .u64 t; cvta.to.shared.u64 t, %1; cvt.u32.u64 %0, t; }" : "=r"(a) : "l"(p));
    return a;
}
__device__ __forceinline__ void cp16(uint32_t dst, const void* src) {
    asm volatile("cp.async.cg.shared.global [%0], [%1], 16;" :: "r"(dst), "l"(src));
}
__device__ __forceinline__ void cp_commit() { asm volatile("cp.async.commit_group;"); }
template<int N> __device__ __forceinline__ void cp_wait() {
    asm volatile("cp.async.wait_group %0;" :: "n"(N));
}
__device__ __forceinline__ void ldm4(uint32_t* r, uint32_t a) {
    asm volatile("ldmatrix.sync.aligned.m8n8.x4.shared.b16 {%0,%1,%2,%3}, [%4];"
                 : "=r"(r[0]), "=r"(r[1]), "=r"(r[2]), "=r"(r[3]) : "r"(a));
}
__device__ __forceinline__ void mma16816(float* c, const uint32_t* a, const uint32_t* b) {
    asm volatile("mma.sync.aligned.m16n8k16.row.col.f32.bf16.bf16.f32 "
                 "{%0,%1,%2,%3},{%4,%5,%6,%7},{%8,%9},{%0,%1,%2,%3};"
                 : "+f"(c[0]), "+f"(c[1]), "+f"(c[2]), "+f"(c[3])
                 : "r"(a[0]), "r"(a[1]), "r"(a[2]), "r"(a[3]), "r"(b[0]), "r"(b[1]));
}
__device__ __forceinline__ unsigned short f2bf(float v) {
    return __bfloat16_as_ushort(__float2bfloat16_rn(v));
}
__device__ __forceinline__ float bf2f(unsigned short u) {
    return __bfloat162float(__ushort_as_bfloat16(u));
}
// packed: 2 floats -> one u32 of two bf16 (low half = first)
__device__ __forceinline__ uint32_t pack_bf2(float a, float b) {
    __nv_bfloat162 h = __float22bfloat162_rn(make_float2(a, b));
    return *(uint32_t*)&h;
}
// cheap split using packed cvt: per 4 floats -> hi uint2, lo uint2
__device__ __forceinline__ void split_store4(unsigned short* hi, unsigned short* lo, float4 o) {
    uint32_t ha = pack_bf2(o.x, o.y);
    uint32_t hb = pack_bf2(o.z, o.w);
    float f0 = __uint_as_float(ha << 16), f1 = __uint_as_float(ha & 0xFFFF0000u);
    float f2 = __uint_as_float(hb << 16), f3 = __uint_as_float(hb & 0xFFFF0000u);
    uint32_t la = pack_bf2(o.x - f0, o.y - f1);
    uint32_t lb = pack_bf2(o.z - f2, o.w - f3);
    *(uint2*)hi = make_uint2(ha, hb);
    *(uint2*)lo = make_uint2(la, lb);
}

// ---------------------------------------------------------------------------
// Kernel 1: KNN — segment-resident smem (<=2 batch segments), 8 thr/point,
// dot-form rank, rare-branch insertion, shfl merge. 512 blocks x 256 thr.
// ---------------------------------------------------------------------------
#define SEG_CAP  2816                 // float4 slots (44KB) -> 5 CTAs/SM
#define KNN_SMEM (SEG_CAP * 16)

__global__ __launch_bounds__(256)
void knn_interp_kernel(const float* __restrict__ x,
                       const float* __restrict__ pos,
                       const int*   __restrict__ batch,
                       const float* __restrict__ x_skip,
                       const float* __restrict__ pos_skip,
                       const int*   __restrict__ batch_skip,
                       const float* __restrict__ W1,
                       const float* __restrict__ W2,
                       float* __restrict__ out, int out_size)
{
    extern __shared__ float4 pos4[];           // [SEG_CAP]
    __shared__ int   sIdx[32][3];
    __shared__ float sW[32][3];
    __shared__ int   sRange[2];                // [seg_lo, seg_hi) union for block

    const int tid = threadIdx.x;
    const int p_local = tid >> 3;
    const int q       = tid & 7;
    const int gp      = blockIdx.x * 32 + p_local;
    const int gid     = blockIdx.x * 256 + tid;

    // ---- block segment union: batches of first/last point in block ----
    if (tid == 0) {
        int mbLo = batch_skip[blockIdx.x * 32];
        int mbHi = batch_skip[blockIdx.x * 32 + 31];
        int lo = 0, hi = NC;
        while (lo < hi) { int m = (lo + hi) >> 1; if (batch[m] < mbLo) lo = m + 1; else hi = m; }
        sRange[0] = lo;
        lo = 0; hi = NC;
        while (lo < hi) { int m = (lo + hi) >> 1; if (batch[m] <= mbHi) lo = m + 1; else hi = m; }
        sRange[1] = lo;
    }

    // ---- weight prep: coalesced reads, scattered transposed writes ----
    for (int i = gid; i < DIN * HID; i += 512 * 256) {
        int k = i >> 8, n = i & 255;
        float v = W1[i];
        unsigned short hh = f2bf(v);
        g_w1[(size_t)n * (2 * DIN) + k]       = hh;
        g_w1[(size_t)n * (2 * DIN) + DIN + k] = f2bf(v - bf2f(hh));
    }
    for (int i = gid; i < HID * HID; i += 512 * 256) {
        int k = i >> 8, n = i & 255;
        float v = W2[i];
        unsigned short hh = f2bf(v);
        g_w2[(size_t)n * (2 * HID) + k]       = hh;
        g_w2[(size_t)n * (2 * HID) + HID + k] = f2bf(v - bf2f(hh));
    }

    __syncthreads();
    const int seg_lo = sRange[0];
    const int seg_hi = sRange[1];
    const int fill_hi = min(seg_hi, seg_lo + SEG_CAP);

    // ---- fill smem with union segment ----
    for (int j = seg_lo + tid; j < fill_hi; j += 256) {
        float cx = pos[3 * j + 0], cy = pos[3 * j + 1], cz = pos[3 * j + 2];
        pos4[j - seg_lo] = make_float4(cx, cy, cz, fmaf(cx, cx, fmaf(cy, cy, cz * cz)));
    }

    // ---- own segment bounds ----
    const float px = pos_skip[3 * gp + 0];
    const float py = pos_skip[3 * gp + 1];
    const float pz = pos_skip[3 * gp + 2];
    const int   mb = batch_skip[gp];

    int lo = 0, hi = NC;
    while (lo < hi) { int m = (lo + hi) >> 1; if (batch[m] < mb) lo = m + 1; else hi = m; }
    const int segs = lo;
    lo = segs; hi = NC;
    while (lo < hi) { int m = (lo + hi) >> 1; if (batch[m] <= mb) lo = m + 1; else hi = m; }
    const int sege = lo;

    __syncthreads();

    // ---- phase 1: eighth-segment scan on d' = |c|^2 - 2 p.c ----
    const float nx = -2.0f * px, ny = -2.0f * py, nz = -2.0f * pz;
    float d0 = 3e38f, d1 = 3e38f, d2 = 3e38f;
    int   i0 = segs,  i1 = segs,  i2 = segs;

    auto ins = [&](float dn, int jn) {
        bool b2 = dn < d2;
        float td = b2 ? dn : d2; int ti = b2 ? jn : i2;
        bool b1 = td < d1;
        d2 = b1 ? d1 : td; i2 = b1 ? i1 : ti;
        float ud = b1 ? td : d1; int ui = b1 ? ti : i1;
        bool b0 = ud < d0;
        d1 = b0 ? d0 : ud; i1 = b0 ? i0 : ui;
        d0 = b0 ? ud : d0; i0 = b0 ? ui : i0;
    };

    const int scan_hi = min(sege, fill_hi);
    #pragma unroll 4
    for (int j = segs + q; j < scan_hi; j += 8) {
        float4 c = pos4[j - seg_lo];
        float s = fmaf(nx, c.x, fmaf(ny, c.y, fmaf(nz, c.z, c.w)));
        if (s < d2) ins(s, j);      // rare
    }
    // overflow safety (astronomically rare): finish from global
    for (int j = max(segs + q, ((scan_hi - segs - q + 7) / 8) * 8 + segs + q); j < sege; j += 8) {
        float cx = pos[3 * j + 0], cy = pos[3 * j + 1], cz = pos[3 * j + 2];
        float cw = fmaf(cx, cx, fmaf(cy, cy, cz * cz));
        float s = fmaf(nx, cx, fmaf(ny, cy, fmaf(nz, cz, cw)));
        if (s < d2) ins(s, j);
    }

    // ---- merge across the 8 lanes of this point ----
    #pragma unroll
    for (int m = 1; m <= 4; m <<= 1) {
        float e0 = __shfl_xor_sync(0xFFFFFFFFu, d0, m);
        float e1 = __shfl_xor_sync(0xFFFFFFFFu, d1, m);
        float e2 = __shfl_xor_sync(0xFFFFFFFFu, d2, m);
        int   f0 = __shfl_xor_sync(0xFFFFFFFFu, i0, m);
        int   f1 = __shfl_xor_sync(0xFFFFFFFFu, i1, m);
        int   f2 = __shfl_xor_sync(0xFFFFFFFFu, i2, m);
        ins(e0, f0); ins(e1, f1); ins(e2, f2);
    }

    if (q == 0) {
        // exact squared distances for the 3 winners (global pos, L2-hit)
        float ax = pos[3 * i0 + 0] - px, ay = pos[3 * i0 + 1] - py, az = pos[3 * i0 + 2] - pz;
        float bx = pos[3 * i1 + 0] - px, by = pos[3 * i1 + 1] - py, bz = pos[3 * i1 + 2] - pz;
        float cx = pos[3 * i2 + 0] - px, cy = pos[3 * i2 + 1] - py, cz = pos[3 * i2 + 2] - pz;
        float e0 = fmaf(ax, ax, fmaf(ay, ay, az * az));
        float e1 = fmaf(bx, bx, fmaf(by, by, bz * bz));
        float e2 = fmaf(cx, cx, fmaf(cy, cy, cz * cz));
        float w0 = 1.0f / fmaxf(e0, 1e-16f);
        float w1v = 1.0f / fmaxf(e1, 1e-16f);
        float w2v = 1.0f / fmaxf(e2, 1e-16f);
        float inv_sw = 1.0f / (w0 + w1v + w2v);
        sIdx[p_local][0] = i0; sIdx[p_local][1] = i1; sIdx[p_local][2] = i2;
        sW[p_local][0] = w0 * inv_sw; sW[p_local][1] = w1v * inv_sw; sW[p_local][2] = w2v * inv_sw;

        if (out_size > NS * HID) {
            out[NS * HID + 3 * gp + 0] = px;
            out[NS * HID + 3 * gp + 1] = py;
            out[NS * HID + 3 * gp + 2] = pz;
            out[NS * HID + NS * 3 + gp] = (float)mb;
        }
    }
    __syncthreads();

    // ---- phase 2: warp-cooperative gather + packed bf16 split store ----
    const int warp = tid >> 5;
    const int lane = tid & 31;

    for (int r = warp; r < 32; r += 8) {
        const int g  = blockIdx.x * 32 + r;
        const int j0 = sIdx[r][0], j1 = sIdx[r][1], j2 = sIdx[r][2];
        const float a = sW[r][0], b = sW[r][1], c = sW[r][2];

        const float4* X0 = (const float4*)(x + (size_t)j0 * CCH);
        const float4* X1 = (const float4*)(x + (size_t)j1 * CCH);
        const float4* X2 = (const float4*)(x + (size_t)j2 * CCH);
        unsigned short* Y = g_ycat + (size_t)g * (2 * DIN);

        #pragma unroll
        for (int v = lane; v < CCH / 4; v += 32) {
            float4 A = X0[v], B = X1[v], Cv = X2[v];
            float4 o;
            o.x = fmaf(a, A.x, fmaf(b, B.x, c * Cv.x));
            o.y = fmaf(a, A.y, fmaf(b, B.y, c * Cv.y));
            o.z = fmaf(a, A.z, fmaf(b, B.z, c * Cv.z));
            o.w = fmaf(a, A.w, fmaf(b, B.w, c * Cv.w));
            split_store4(Y + v * 4, Y + DIN + v * 4, o);
        }
        float4 sv = ((const float4*)(x_skip + (size_t)g * CS))[lane];
        split_store4(Y + CCH + lane * 4, Y + DIN + CCH + lane * 4, sv);
    }
}

// ---------------------------------------------------------------------------
// bf16x3 mma.sync GEMM: C[M,256] = relu(A @ B^T + bias)
// CTA tile 128x128, BK=32, 256 threads (8 warps = 4m x 2n), 3-stage cp.async.
// ---------------------------------------------------------------------------
#define GSTAGES 3
#define GEMM_SMEM (GSTAGES * 32768)

template<int K, bool PACK>
__global__ __launch_bounds__(256, 1)
void mma_gemm(const unsigned short* __restrict__ Apk,
              const unsigned short* __restrict__ Bpk,
              const float* __restrict__ bias,
              void* __restrict__ Cout)
{
    constexpr int NCHK = K / 32;
    extern __shared__ uint8_t smem[];
    const uint32_t sb = smem_u32(smem);

    const int tid   = threadIdx.x;
    const int lane  = tid & 31;
    const int wid   = tid >> 5;
    const int warpM = wid & 3;
    const int warpN = wid >> 2;
    const int m0    = blockIdx.x * 128;
    const int n0    = blockIdx.y * 128;

    const uint8_t* Abytes = (const uint8_t*)Apk + (size_t)m0 * (4 * K);
    const uint8_t* Bbytes = (const uint8_t*)Bpk + (size_t)n0 * (4 * K);

    auto issue = [&](int kc, int st) {
        uint32_t sA = sb + st * 32768, sB = sA + 16384;
        #pragma unroll
        for (int i = 0; i < 4; ++i) {
            int id  = tid + 256 * i;
            int row = id >> 3, g = id & 7;
            int off = row * (4 * K) + (g < 4 ? kc * 64 + g * 16
                                             : 2 * K + kc * 64 + (g - 4) * 16);
            uint32_t d = (uint32_t)(row * 128) + (uint32_t)((g ^ (row & 7)) << 4);
            cp16(sA + d, Abytes + off);
            cp16(sB + d, Bbytes + off);
        }
        cp_commit();
    };

    issue(0, 0);
    issue(1, 1);

    float acc[2][8][4] = {};

    for (int c = 0; c < NCHK; ++c) {
        if (c <= NCHK - 2) cp_wait<1>(); else cp_wait<0>();
        __syncthreads();

        const int st = c % GSTAGES;
        const uint32_t sA = sb + st * 32768, sB = sA + 16384;

        #pragma unroll
        for (int kk = 0; kk < 2; ++kk) {
            uint32_t ah[2][4], al[2][4];
            #pragma unroll
            for (int mf = 0; mf < 2; ++mf) {
                const int rm  = warpM * 32 + mf * 16 + (lane & 15);
                const int sub = lane >> 4;
                const uint32_t base = sA + rm * 128;
                ldm4(ah[mf], base + (((kk * 2 + sub) ^ (rm & 7)) << 4));
                ldm4(al[mf], base + (((4 + kk * 2 + sub) ^ (rm & 7)) << 4));
            }
            uint32_t bh[8][2], bl[8][2];
            #pragma unroll
            for (int nq = 0; nq < 4; ++nq) {
                const int rn  = warpN * 64 + nq * 16 + (lane & 7) + ((lane >> 4) << 3);
                const int sub = (lane >> 3) & 1;
                const uint32_t base = sB + rn * 128;
                uint32_t t[4];
                ldm4(t, base + (((kk * 2 + sub) ^ (rn & 7)) << 4));
                bh[2 * nq][0] = t[0]; bh[2 * nq][1] = t[1];
                bh[2 * nq + 1][0] = t[2]; bh[2 * nq + 1][1] = t[3];
                ldm4(t, base + (((4 + kk * 2 + sub) ^ (rn & 7)) << 4));
                bl[2 * nq][0] = t[0]; bl[2 * nq][1] = t[1];
                bl[2 * nq + 1][0] = t[2]; bl[2 * nq + 1][1] = t[3];
            }
            #pragma unroll
            for (int mf = 0; mf < 2; ++mf)
                #pragma unroll
                for (int nf = 0; nf < 8; ++nf) {
                    mma16816(acc[mf][nf], ah[mf], bh[nf]);
                    mma16816(acc[mf][nf], ah[mf], bl[nf]);
                    mma16816(acc[mf][nf], al[mf], bh[nf]);
                }
        }

        if (c + GSTAGES - 1 < NCHK) issue(c + GSTAGES - 1, (c + GSTAGES - 1) % GSTAGES);
    }

    #pragma unroll
    for (int mf = 0; mf < 2; ++mf) {
        const int mrow = m0 + warpM * 32 + mf * 16 + (lane >> 2);
        #pragma unroll
        for (int nf = 0; nf < 8; ++nf) {
            const int n = n0 + warpN * 64 + nf * 8 + 2 * (lane & 3);
            const float b0v = __ldg(bias + n), b1v = __ldg(bias + n + 1);
            float v00 = fmaxf(acc[mf][nf][0] + b0v, 0.0f);
            float v01 = fmaxf(acc[mf][nf][1] + b1v, 0.0f);
            float v10 = fmaxf(acc[mf][nf][2] + b0v, 0.0f);
            float v11 = fmaxf(acc[mf][nf][3] + b1v, 0.0f);
            if (PACK) {
                unsigned short* H = (unsigned short*)Cout;
                uint32_t hi0 = pack_bf2(v00, v01);
                float g0 = __uint_as_float(hi0 << 16), g1 = __uint_as_float(hi0 & 0xFFFF0000u);
                uint32_t lo0 = pack_bf2(v00 - g0, v01 - g1);
                uint32_t hi1 = pack_bf2(v10, v11);
                float g2 = __uint_as_float(hi1 << 16), g3 = __uint_as_float(hi1 & 0xFFFF0000u);
                uint32_t lo1 = pack_bf2(v10 - g2, v11 - g3);
                *(uint32_t*)(H + (size_t)mrow * (2 * HID) + n)             = hi0;
                *(uint32_t*)(H + (size_t)mrow * (2 * HID) + HID + n)       = lo0;
                *(uint32_t*)(H + (size_t)(mrow + 8) * (2 * HID) + n)       = hi1;
                *(uint32_t*)(H + (size_t)(mrow + 8) * (2 * HID) + HID + n) = lo1;
            } else {
                float* O = (float*)Cout;
                float2 p0 = {v00, v01}, p1 = {v10, v11};
                *(float2*)(O + (size_t)mrow * 256 + n)       = p0;
                *(float2*)(O + (size_t)(mrow + 8) * 256 + n) = p1;
            }
        }
    }
}

// ---------------------------------------------------------------------------
extern "C" void kernel_launch(void* const* d_in, const int* in_sizes, int n_in,
                              void* d_out, int out_size)
{
    const float* x          = (const float*)d_in[0];
    const float* pos        = (const float*)d_in[1];
    const int*   batch      = (const int*)  d_in[2];
    const float* x_skip     = (const float*)d_in[3];
    const float* pos_skip   = (const float*)d_in[4];
    const int*   batch_skip = (const int*)  d_in[5];
    const float* W1         = (const float*)d_in[6];
    const float* b1         = (const float*)d_in[7];
    const float* W2         = (const float*)d_in[8];
    const float* b2         = (const float*)d_in[9];
    float* out = (float*)d_out;

    unsigned short *ycat, *h, *w1, *w2;
    cudaGetSymbolAddress((void**)&ycat, g_ycat);
    cudaGetSymbolAddress((void**)&h,    g_h);
    cudaGetSymbolAddress((void**)&w1,   g_w1);
    cudaGetSymbolAddress((void**)&w2,   g_w2);

    cudaFuncSetAttribute(knn_interp_kernel,    cudaFuncAttributeMaxDynamicSharedMemorySize, KNN_SMEM);
    cudaFuncSetAttribute(mma_gemm<DIN, true>,  cudaFuncAttributeMaxDynamicSharedMemorySize, GEMM_SMEM);
    cudaFuncSetAttribute(mma_gemm<HID, false>, cudaFuncAttributeMaxDynamicSharedMemorySize, GEMM_SMEM);

    // 1) KNN + interpolate + concat (+ weight prep + tail outputs)
    knn_interp_kernel<<<NS / 32, 256, KNN_SMEM>>>(x, pos, batch, x_skip, pos_skip, batch_skip,
                                                  W1, W2, out, out_size);

    // 2) h = relu(ycat @ W1 + b1)  — packed bf16 output
    {
        dim3 grid(NS / 128, 2);
        mma_gemm<DIN, true><<<grid, 256, GEMM_SMEM>>>(ycat, w1, b1, h);
    }
    // 3) out = relu(h @ W2 + b2)   — fp32 output
    {
        dim3 grid(NS / 128, 2);
        mma_gemm<HID, false><<<grid, 256, GEMM_SMEM>>>(h, w2, b2, out);
    }
}

// round 8
// speedup vs baseline: 3.1232x; 1.0332x over previous
#include <cuda_runtime.h>
#include <cuda_bf16.h>
#include <cstdint>

#define NC   4096
#define NS   16384
#define CCH  256
#define CS   128
#define DIN  384
#define HID  256

// Packed split-bf16 activation/weight buffers: row m = [hi(K) | lo(K)] bf16.
__device__ __align__(16) unsigned short g_ycat[(size_t)NS * (2 * DIN)];
__device__ __align__(16) unsigned short g_h[(size_t)NS * (2 * HID)];
__device__ __align__(16) unsigned short g_w1[(size_t)HID * (2 * DIN)];
__device__ __align__(16) unsigned short g_w2[(size_t)HID * (2 * HID)];

// ---------------------------------------------------------------------------
// helpers
// ---------------------------------------------------------------------------
__device__ __forceinline__ uint32_t smem_u32(const void* p) {
    uint32_t a;
    asm("{ .reg .u64 t; cvta.to.shared.u64 t, %1; cvt.u32.u64 %0, t; }" : "=r"(a) : "l"(p));
    return a;
}
__device__ __forceinline__ void cp16(uint32_t dst, const void* src) {
    asm volatile("cp.async.cg.shared.global [%0], [%1], 16;" :: "r"(dst), "l"(src));
}
__device__ __forceinline__ void cp_commit() { asm volatile("cp.async.commit_group;"); }
template<int N> __device__ __forceinline__ void cp_wait() {
    asm volatile("cp.async.wait_group %0;" :: "n"(N));
}
__device__ __forceinline__ void ldm4(uint32_t* r, uint32_t a) {
    asm volatile("ldmatrix.sync.aligned.m8n8.x4.shared.b16 {%0,%1,%2,%3}, [%4];"
                 : "=r"(r[0]), "=r"(r[1]), "=r"(r[2]), "=r"(r[3]) : "r"(a));
}
__device__ __forceinline__ void mma16816(float* c, const uint32_t* a, const uint32_t* b) {
    asm volatile("mma.sync.aligned.m16n8k16.row.col.f32.bf16.bf16.f32 "
                 "{%0,%1,%2,%3},{%4,%5,%6,%7},{%8,%9},{%0,%1,%2,%3};"
                 : "+f"(c[0]), "+f"(c[1]), "+f"(c[2]), "+f"(c[3])
                 : "r"(a[0]), "r"(a[1]), "r"(a[2]), "r"(a[3]), "r"(b[0]), "r"(b[1]));
}
__device__ __forceinline__ unsigned short f2bf(float v) {
    return __bfloat16_as_ushort(__float2bfloat16_rn(v));
}
__device__ __forceinline__ float bf2f(unsigned short u) {
    return __bfloat162float(__ushort_as_bfloat16(u));
}
__device__ __forceinline__ uint32_t pack_bf2(float a, float b) {
    __nv_bfloat162 h = __float22bfloat162_rn(make_float2(a, b));
    return *(uint32_t*)&h;
}
__device__ __forceinline__ void split_store4(unsigned short* hi, unsigned short* lo, float4 o) {
    uint32_t ha = pack_bf2(o.x, o.y);
    uint32_t hb = pack_bf2(o.z, o.w);
    float f0 = __uint_as_float(ha << 16), f1 = __uint_as_float(ha & 0xFFFF0000u);
    float f2 = __uint_as_float(hb << 16), f3 = __uint_as_float(hb & 0xFFFF0000u);
    uint32_t la = pack_bf2(o.x - f0, o.y - f1);
    uint32_t lb = pack_bf2(o.z - f2, o.w - f3);
    *(uint2*)hi = make_uint2(ha, hb);
    *(uint2*)lo = make_uint2(la, lb);
}

// ---------------------------------------------------------------------------
// Kernel 1: KNN — segment-resident smem (26KB -> 8 CTAs/SM), 8 thr/point,
// shared batch-boundary table, dot-form rank, rare-branch insertion.
// ---------------------------------------------------------------------------
#define SEG_CAP  1664                 // float4 slots (26KB)
#define KNN_SMEM (SEG_CAP * 16)
#define NBATCH   4

__global__ __launch_bounds__(256, 8)
void knn_interp_kernel(const float* __restrict__ x,
                       const float* __restrict__ pos,
                       const int*   __restrict__ batch,
                       const float* __restrict__ x_skip,
                       const float* __restrict__ pos_skip,
                       const int*   __restrict__ batch_skip,
                       const float* __restrict__ W1,
                       const float* __restrict__ W2,
                       float* __restrict__ out, int out_size)
{
    extern __shared__ float4 pos4[];           // [SEG_CAP]
    __shared__ int   sIdx[32][3];
    __shared__ float sW[32][3];
    __shared__ int   sSegB[NBATCH + 1];        // batch segment boundaries

    const int tid = threadIdx.x;
    const int p_local = tid >> 3;
    const int q       = tid & 7;
    const int gp      = blockIdx.x * 32 + p_local;
    const int gid     = blockIdx.x * 256 + tid;

    // ---- batch boundary table (5 threads, one binary search each) ----
    if (tid <= NBATCH) {
        int b = tid;
        int v;
        if (b == 0) v = 0;
        else if (b == NBATCH) v = NC;
        else {
            int lo = 0, hi = NC;
            while (lo < hi) { int m = (lo + hi) >> 1; if (batch[m] < b) lo = m + 1; else hi = m; }
            v = lo;
        }
        sSegB[b] = v;
    }

    // ---- weight prep: coalesced reads, scattered transposed writes ----
    for (int i = gid; i < DIN * HID; i += 512 * 256) {
        int k = i >> 8, n = i & 255;
        float v = W1[i];
        unsigned short hh = f2bf(v);
        g_w1[(size_t)n * (2 * DIN) + k]       = hh;
        g_w1[(size_t)n * (2 * DIN) + DIN + k] = f2bf(v - bf2f(hh));
    }
    for (int i = gid; i < HID * HID; i += 512 * 256) {
        int k = i >> 8, n = i & 255;
        float v = W2[i];
        unsigned short hh = f2bf(v);
        g_w2[(size_t)n * (2 * HID) + k]       = hh;
        g_w2[(size_t)n * (2 * HID) + HID + k] = f2bf(v - bf2f(hh));
    }

    __syncthreads();

    // ---- block segment union + own bounds from the table ----
    const int mbLo = batch_skip[blockIdx.x * 32];
    const int mbHi = batch_skip[blockIdx.x * 32 + 31];
    const int seg_lo  = sSegB[mbLo];
    const int fill_hi = min(sSegB[mbHi + 1], seg_lo + SEG_CAP);

    const float px = pos_skip[3 * gp + 0];
    const float py = pos_skip[3 * gp + 1];
    const float pz = pos_skip[3 * gp + 2];
    const int   mb = batch_skip[gp];
    const int   segs = sSegB[mb];
    const int   sege = sSegB[mb + 1];

    // ---- fill smem with union segment ----
    for (int j = seg_lo + tid; j < fill_hi; j += 256) {
        float cx = pos[3 * j + 0], cy = pos[3 * j + 1], cz = pos[3 * j + 2];
        pos4[j - seg_lo] = make_float4(cx, cy, cz, fmaf(cx, cx, fmaf(cy, cy, cz * cz)));
    }
    __syncthreads();

    // ---- phase 1: eighth-segment scan on d' = |c|^2 - 2 p.c ----
    const float nx = -2.0f * px, ny = -2.0f * py, nz = -2.0f * pz;
    float d0 = 3e38f, d1 = 3e38f, d2 = 3e38f;
    int   i0 = segs,  i1 = segs,  i2 = segs;

    auto ins = [&](float dn, int jn) {
        bool b2 = dn < d2;
        float td = b2 ? dn : d2; int ti = b2 ? jn : i2;
        bool b1 = td < d1;
        d2 = b1 ? d1 : td; i2 = b1 ? i1 : ti;
        float ud = b1 ? td : d1; int ui = b1 ? ti : i1;
        bool b0 = ud < d0;
        d1 = b0 ? d0 : ud; i1 = b0 ? i0 : ui;
        d0 = b0 ? ud : d0; i0 = b0 ? ui : i0;
    };

    const int scan_hi = min(sege, fill_hi);
    #pragma unroll 4
    for (int j = segs + q; j < scan_hi; j += 8) {
        float4 c = pos4[j - seg_lo];
        float s = fmaf(nx, c.x, fmaf(ny, c.y, fmaf(nz, c.z, c.w)));
        if (s < d2) ins(s, j);      // rare
    }
    // overflow safety (boundary blocks only): finish from global
    for (int j = max(segs + q, ((scan_hi - segs - q + 7) / 8) * 8 + segs + q); j < sege; j += 8) {
        float cx = pos[3 * j + 0], cy = pos[3 * j + 1], cz = pos[3 * j + 2];
        float cw = fmaf(cx, cx, fmaf(cy, cy, cz * cz));
        float s = fmaf(nx, cx, fmaf(ny, cy, fmaf(nz, cz, cw)));
        if (s < d2) ins(s, j);
    }

    // ---- merge across the 8 lanes of this point ----
    #pragma unroll
    for (int m = 1; m <= 4; m <<= 1) {
        float e0 = __shfl_xor_sync(0xFFFFFFFFu, d0, m);
        float e1 = __shfl_xor_sync(0xFFFFFFFFu, d1, m);
        float e2 = __shfl_xor_sync(0xFFFFFFFFu, d2, m);
        int   f0 = __shfl_xor_sync(0xFFFFFFFFu, i0, m);
        int   f1 = __shfl_xor_sync(0xFFFFFFFFu, i1, m);
        int   f2 = __shfl_xor_sync(0xFFFFFFFFu, i2, m);
        ins(e0, f0); ins(e1, f1); ins(e2, f2);
    }

    if (q == 0) {
        // exact squared distances for the 3 winners (global pos, L2-hit)
        float ax = pos[3 * i0 + 0] - px, ay = pos[3 * i0 + 1] - py, az = pos[3 * i0 + 2] - pz;
        float bx = pos[3 * i1 + 0] - px, by = pos[3 * i1 + 1] - py, bz = pos[3 * i1 + 2] - pz;
        float cx = pos[3 * i2 + 0] - px, cy = pos[3 * i2 + 1] - py, cz = pos[3 * i2 + 2] - pz;
        float e0 = fmaf(ax, ax, fmaf(ay, ay, az * az));
        float e1 = fmaf(bx, bx, fmaf(by, by, bz * bz));
        float e2 = fmaf(cx, cx, fmaf(cy, cy, cz * cz));
        float w0 = 1.0f / fmaxf(e0, 1e-16f);
        float w1v = 1.0f / fmaxf(e1, 1e-16f);
        float w2v = 1.0f / fmaxf(e2, 1e-16f);
        float inv_sw = 1.0f / (w0 + w1v + w2v);
        sIdx[p_local][0] = i0; sIdx[p_local][1] = i1; sIdx[p_local][2] = i2;
        sW[p_local][0] = w0 * inv_sw; sW[p_local][1] = w1v * inv_sw; sW[p_local][2] = w2v * inv_sw;

        if (out_size > NS * HID) {
            out[NS * HID + 3 * gp + 0] = px;
            out[NS * HID + 3 * gp + 1] = py;
            out[NS * HID + 3 * gp + 2] = pz;
            out[NS * HID + NS * 3 + gp] = (float)mb;
        }
    }
    __syncthreads();

    // ---- phase 2: warp-cooperative gather + packed bf16 split store ----
    const int warp = tid >> 5;
    const int lane = tid & 31;

    for (int r = warp; r < 32; r += 8) {
        const int g  = blockIdx.x * 32 + r;
        const int j0 = sIdx[r][0], j1 = sIdx[r][1], j2 = sIdx[r][2];
        const float a = sW[r][0], b = sW[r][1], c = sW[r][2];

        const float4* X0 = (const float4*)(x + (size_t)j0 * CCH);
        const float4* X1 = (const float4*)(x + (size_t)j1 * CCH);
        const float4* X2 = (const float4*)(x + (size_t)j2 * CCH);
        unsigned short* Y = g_ycat + (size_t)g * (2 * DIN);

        #pragma unroll
        for (int v = lane; v < CCH / 4; v += 32) {
            float4 A = X0[v], B = X1[v], Cv = X2[v];
            float4 o;
            o.x = fmaf(a, A.x, fmaf(b, B.x, c * Cv.x));
            o.y = fmaf(a, A.y, fmaf(b, B.y, c * Cv.y));
            o.z = fmaf(a, A.z, fmaf(b, B.z, c * Cv.z));
            o.w = fmaf(a, A.w, fmaf(b, B.w, c * Cv.w));
            split_store4(Y + v * 4, Y + DIN + v * 4, o);
        }
        float4 sv = ((const float4*)(x_skip + (size_t)g * CS))[lane];
        split_store4(Y + CCH + lane * 4, Y + DIN + CCH + lane * 4, sv);
    }
}

// ---------------------------------------------------------------------------
// bf16x3 mma.sync GEMM: C[M,256] = relu(A @ B^T + bias)
// CTA tile 128x128, BK=32, 256 threads (8 warps = 4m x 2n), 3-stage cp.async.
// ---------------------------------------------------------------------------
#define GSTAGES 3
#define GEMM_SMEM (GSTAGES * 32768)

template<int K, bool PACK>
__global__ __launch_bounds__(256, 1)
void mma_gemm(const unsigned short* __restrict__ Apk,
              const unsigned short* __restrict__ Bpk,
              const float* __restrict__ bias,
              void* __restrict__ Cout)
{
    constexpr int NCHK = K / 32;
    extern __shared__ uint8_t smem[];
    const uint32_t sb = smem_u32(smem);

    const int tid   = threadIdx.x;
    const int lane  = tid & 31;
    const int wid   = tid >> 5;
    const int warpM = wid & 3;
    const int warpN = wid >> 2;
    const int m0    = blockIdx.x * 128;
    const int n0    = blockIdx.y * 128;

    const uint8_t* Abytes = (const uint8_t*)Apk + (size_t)m0 * (4 * K);
    const uint8_t* Bbytes = (const uint8_t*)Bpk + (size_t)n0 * (4 * K);

    auto issue = [&](int kc, int st) {
        uint32_t sA = sb + st * 32768, sB = sA + 16384;
        #pragma unroll
        for (int i = 0; i < 4; ++i) {
            int id  = tid + 256 * i;
            int row = id >> 3, g = id & 7;
            int off = row * (4 * K) + (g < 4 ? kc * 64 + g * 16
                                             : 2 * K + kc * 64 + (g - 4) * 16);
            uint32_t d = (uint32_t)(row * 128) + (uint32_t)((g ^ (row & 7)) << 4);
            cp16(sA + d, Abytes + off);
            cp16(sB + d, Bbytes + off);
        }
        cp_commit();
    };

    issue(0, 0);
    issue(1, 1);

    float acc[2][8][4] = {};

    for (int c = 0; c < NCHK; ++c) {
        if (c <= NCHK - 2) cp_wait<1>(); else cp_wait<0>();
        __syncthreads();

        const int st = c % GSTAGES;
        const uint32_t sA = sb + st * 32768, sB = sA + 16384;

        #pragma unroll
        for (int kk = 0; kk < 2; ++kk) {
            uint32_t ah[2][4], al[2][4];
            #pragma unroll
            for (int mf = 0; mf < 2; ++mf) {
                const int rm  = warpM * 32 + mf * 16 + (lane & 15);
                const int sub = lane >> 4;
                const uint32_t base = sA + rm * 128;
                ldm4(ah[mf], base + (((kk * 2 + sub) ^ (rm & 7)) << 4));
                ldm4(al[mf], base + (((4 + kk * 2 + sub) ^ (rm & 7)) << 4));
            }
            uint32_t bh[8][2], bl[8][2];
            #pragma unroll
            for (int nq = 0; nq < 4; ++nq) {
                const int rn  = warpN * 64 + nq * 16 + (lane & 7) + ((lane >> 4) << 3);
                const int sub = (lane >> 3) & 1;
                const uint32_t base = sB + rn * 128;
                uint32_t t[4];
                ldm4(t, base + (((kk * 2 + sub) ^ (rn & 7)) << 4));
                bh[2 * nq][0] = t[0]; bh[2 * nq][1] = t[1];
                bh[2 * nq + 1][0] = t[2]; bh[2 * nq + 1][1] = t[3];
                ldm4(t, base + (((4 + kk * 2 + sub) ^ (rn & 7)) << 4));
                bl[2 * nq][0] = t[0]; bl[2 * nq][1] = t[1];
                bl[2 * nq + 1][0] = t[2]; bl[2 * nq + 1][1] = t[3];
            }
            #pragma unroll
            for (int mf = 0; mf < 2; ++mf)
                #pragma unroll
                for (int nf = 0; nf < 8; ++nf) {
                    mma16816(acc[mf][nf], ah[mf], bh[nf]);
                    mma16816(acc[mf][nf], ah[mf], bl[nf]);
                    mma16816(acc[mf][nf], al[mf], bh[nf]);
                }
        }

        if (c + GSTAGES - 1 < NCHK) issue(c + GSTAGES - 1, (c + GSTAGES - 1) % GSTAGES);
    }

    #pragma unroll
    for (int mf = 0; mf < 2; ++mf) {
        const int mrow = m0 + warpM * 32 + mf * 16 + (lane >> 2);
        #pragma unroll
        for (int nf = 0; nf < 8; ++nf) {
            const int n = n0 + warpN * 64 + nf * 8 + 2 * (lane & 3);
            const float b0v = __ldg(bias + n), b1v = __ldg(bias + n + 1);
            float v00 = fmaxf(acc[mf][nf][0] + b0v, 0.0f);
            float v01 = fmaxf(acc[mf][nf][1] + b1v, 0.0f);
            float v10 = fmaxf(acc[mf][nf][2] + b0v, 0.0f);
            float v11 = fmaxf(acc[mf][nf][3] + b1v, 0.0f);
            if (PACK) {
                unsigned short* H = (unsigned short*)Cout;
                uint32_t hi0 = pack_bf2(v00, v01);
                float g0 = __uint_as_float(hi0 << 16), g1 = __uint_as_float(hi0 & 0xFFFF0000u);
                uint32_t lo0 = pack_bf2(v00 - g0, v01 - g1);
                uint32_t hi1 = pack_bf2(v10, v11);
                float g2 = __uint_as_float(hi1 << 16), g3 = __uint_as_float(hi1 & 0xFFFF0000u);
                uint32_t lo1 = pack_bf2(v10 - g2, v11 - g3);
                *(uint32_t*)(H + (size_t)mrow * (2 * HID) + n)             = hi0;
                *(uint32_t*)(H + (size_t)mrow * (2 * HID) + HID + n)       = lo0;
                *(uint32_t*)(H + (size_t)(mrow + 8) * (2 * HID) + n)       = hi1;
                *(uint32_t*)(H + (size_t)(mrow + 8) * (2 * HID) + HID + n) = lo1;
            } else {
                float* O = (float*)Cout;
                float2 p0 = {v00, v01}, p1 = {v10, v11};
                *(float2*)(O + (size_t)mrow * 256 + n)       = p0;
                *(float2*)(O + (size_t)(mrow + 8) * 256 + n) = p1;
            }
        }
    }
}

// ---------------------------------------------------------------------------
extern "C" void kernel_launch(void* const* d_in, const int* in_sizes, int n_in,
                              void* d_out, int out_size)
{
    const float* x          = (const float*)d_in[0];
    const float* pos        = (const float*)d_in[1];
    const int*   batch      = (const int*)  d_in[2];
    const float* x_skip     = (const float*)d_in[3];
    const float* pos_skip   = (const float*)d_in[4];
    const int*   batch_skip = (const int*)  d_in[5];
    const float* W1         = (const float*)d_in[6];
    const float* b1         = (const float*)d_in[7];
    const float* W2         = (const float*)d_in[8];
    const float* b2         = (const float*)d_in[9];
    float* out = (float*)d_out;

    unsigned short *ycat, *h, *w1, *w2;
    cudaGetSymbolAddress((void**)&ycat, g_ycat);
    cudaGetSymbolAddress((void**)&h,    g_h);
    cudaGetSymbolAddress((void**)&w1,   g_w1);
    cudaGetSymbolAddress((void**)&w2,   g_w2);

    cudaFuncSetAttribute(knn_interp_kernel,    cudaFuncAttributeMaxDynamicSharedMemorySize, KNN_SMEM);
    cudaFuncSetAttribute(mma_gemm<DIN, true>,  cudaFuncAttributeMaxDynamicSharedMemorySize, GEMM_SMEM);
    cudaFuncSetAttribute(mma_gemm<HID, false>, cudaFuncAttributeMaxDynamicSharedMemorySize, GEMM_SMEM);

    // 1) KNN + interpolate + concat (+ weight prep + tail outputs)
    knn_interp_kernel<<<NS / 32, 256, KNN_SMEM>>>(x, pos, batch, x_skip, pos_skip, batch_skip,
                                                  W1, W2, out, out_size);

    // 2) h = relu(ycat @ W1 + b1)  — packed bf16 output
    {
        dim3 grid(NS / 128, 2);
        mma_gemm<DIN, true><<<grid, 256, GEMM_SMEM>>>(ycat, w1, b1, h);
    }
    // 3) out = relu(h @ W2 + b2)   — fp32 output
    {
        dim3 grid(NS / 128, 2);
        mma_gemm<HID, false><<<grid, 256, GEMM_SMEM>>>(h, w2, b2, out);
    }
}